// round 9
// baseline (speedup 1.0000x reference)
#include <cuda_runtime.h>
#include <cuda_fp16.h>
#include <stdint.h>

// Problem constants
#define GAMMA   0.001f
#define DIM     512
#define NTEST   8192
#define NTRAIN  8192
#define NOUT    16

// Tiling
#define BM      128
#define BN      256
#define KT      64                  // fp16 K per chunk
#define KCHUNKS (DIM / KT)          // 8

// SMEM: stage = A(128 x 144B) + B(256 x 144B) = 55296B, 2 stages
#define PITCH       144
#define A_TILE      (128 * PITCH)            // 18432
#define B_TILE      (256 * PITCH)            // 36864
#define STAGE_BYTES (A_TILE + B_TILE)        // 55296
#define OFF_ASH     (2 * STAGE_BYTES)        // 110592: alpha fp16 256 x 48B
#define SMEM_BYTES  (OFF_ASH + 12288)        // 122880 -> 1 CTA/SM
#define WS_PITCH    528                      // fp16 W' [128][256] row pitch

// Device scratch
__device__ __half g_Xh[NTEST * DIM];
__device__ __half g_Yh[NTRAIN * DIM];
__device__ float  g_xs[NTEST];           // exp(-gamma*||x||^2)
__device__ float  g_as[NTRAIN * NOUT];   // alpha * exp(-gamma*||y||^2)
__device__ float  g_S[NOUT];             // column sums of g_as

// ---------------------------------------------------------------------------
__device__ __forceinline__ uint32_t smem_u32(const void* p) {
    uint32_t a;
    asm("{ .reg .u64 t; cvta.to.shared.u64 t, %1; cvt.u32.u64 %0, t; }"
        : "=r"(a) : "l"(p));
    return a;
}
__device__ __forceinline__ void cp16(uint32_t dst, const void* src) {
    asm volatile("cp.async.cg.shared.global [%0], [%1], 16;"
                 :: "r"(dst), "l"(src));
}
#define CP_COMMIT() asm volatile("cp.async.commit_group;" ::: "memory")
#define CP_WAIT(n)  asm volatile("cp.async.wait_group %0;" :: "n"(n) : "memory")

#define LDMX4(r, addr) \
    asm volatile("ldmatrix.sync.aligned.m8n8.x4.shared.b16 {%0,%1,%2,%3}, [%4];" \
        : "=r"((r)[0]), "=r"((r)[1]), "=r"((r)[2]), "=r"((r)[3]) : "r"(addr))

#define LDMX4T(r, addr) \
    asm volatile("ldmatrix.sync.aligned.m8n8.x4.trans.shared.b16 {%0,%1,%2,%3}, [%4];" \
        : "=r"((r)[0]), "=r"((r)[1]), "=r"((r)[2]), "=r"((r)[3]) : "r"(addr))

#define MMAF16(c, a, b0, b1) \
    asm volatile("mma.sync.aligned.m16n8k16.row.col.f32.f16.f16.f32 " \
        "{%0,%1,%2,%3}, {%4,%5,%6,%7}, {%8,%9}, {%0,%1,%2,%3};" \
        : "+f"((c)[0]), "+f"((c)[1]), "+f"((c)[2]), "+f"((c)[3]) \
        : "r"((a)[0]), "r"((a)[1]), "r"((a)[2]), "r"((a)[3]), "r"(b0), "r"(b1))

// ---------------------------------------------------------------------------
__global__ void zero_s_kernel() {
    if (threadIdx.x < NOUT) g_S[threadIdx.x] = 0.0f;
}

// Prep: fp32 -> fp16 + norm folding + global alpha column sums.
__global__ void prep_kernel(const float* __restrict__ X,
                            const float* __restrict__ TX,
                            const float* __restrict__ alpha) {
    const int row = blockIdx.x;
    const bool train = (row >= NTEST);
    const int r = train ? row - NTEST : row;
    const float* src = train ? TX + (size_t)r * DIM : X + (size_t)r * DIM;
    __half* dst = train ? g_Yh + (size_t)r * DIM : g_Xh + (size_t)r * DIM;

    float4 v = ((const float4*)src)[threadIdx.x];
    __half2* d2 = (__half2*)dst;
    d2[threadIdx.x * 2]     = __floats2half2_rn(v.x, v.y);
    d2[threadIdx.x * 2 + 1] = __floats2half2_rn(v.z, v.w);

    float s = v.x * v.x + v.y * v.y + v.z * v.z + v.w * v.w;
    #pragma unroll
    for (int off = 16; off > 0; off >>= 1)
        s += __shfl_down_sync(0xffffffffu, s, off);
    __shared__ float red[4];
    if ((threadIdx.x & 31) == 0) red[threadIdx.x >> 5] = s;
    __syncthreads();
    if (threadIdx.x < NOUT) {
        float e = __expf(-GAMMA * (red[0] + red[1] + red[2] + red[3]));
        if (train) {
            float val = alpha[r * NOUT + threadIdx.x] * e;
            g_as[r * NOUT + threadIdx.x] = val;
            atomicAdd(&g_S[threadIdx.x], val);
        } else if (threadIdx.x == 0) {
            g_xs[r] = e;
        }
    }
}

// Init: out[r][o] = xs[r] * S[o]   (the "+1" part of W = 1 + w')
__global__ void init_out_kernel(float* __restrict__ out) {
    int i = blockIdx.x * 256 + threadIdx.x;
    out[i] = g_xs[i >> 4] * g_S[i & 15];
}

// ---------------------------------------------------------------------------
// Main: 128x256 fp16 HMMA GEMM (K=512), KT=64, 2-stage cp.async,
// fragment double-buffering; epilogue: w'=exp(2g c)-1 fp16, HMMA GEMV.
// 8 warps: warp_m = wid&1 (2), warp_n = wid>>1 (4); warp tile 64x64.
// ---------------------------------------------------------------------------
__global__ __launch_bounds__(256, 1)
void rbf_hmma_kernel(float* __restrict__ out) {
    extern __shared__ __align__(1024) uint8_t smem[];
    const uint32_t sb = smem_u32(smem);

    const int tid    = threadIdx.x;
    const int lane   = tid & 31;
    const int wid    = tid >> 5;
    const int warp_m = wid & 1;      // 0..1
    const int warp_n = wid >> 1;     // 0..3
    const int row0   = blockIdx.x * BM;
    const int j0     = blockIdx.y * BN;

    // ldmatrix per-lane base byte offsets within a stage (144B pitch)
    const uint32_t aoff =
        (uint32_t)(warp_m * 64 + ((lane >> 3) & 1) * 8 + (lane & 7)) * PITCH
        + (uint32_t)(lane >> 4) * 16;
    const uint32_t boff = A_TILE +
        (uint32_t)(warp_n * 64 + ((lane >> 4) & 1) * 8 + (lane & 7)) * PITCH
        + (uint32_t)((lane >> 3) & 1) * 16;

    // cp.async: thread -> (row tid>>3, granule tid&7); hoisted pointers
    const int cprow = tid >> 3;          // 0..31
    const int cpkg  = tid & 7;
    const __half* xsrc = g_Xh + (size_t)(row0 + cprow) * DIM + cpkg * 8;
    const __half* ysrc = g_Yh + (size_t)(j0   + cprow) * DIM + cpkg * 8;
    const uint32_t cpdst = (uint32_t)cprow * PITCH + (uint32_t)cpkg * 16;
    const uint32_t ROWSTEP = 32 * DIM;   // elements per +32 rows

    // Stage the scaled-alpha tile as fp16 [256 rows][48B pitch]
    {
        const float4* src = (const float4*)(g_as + (size_t)j0 * NOUT);
        #pragma unroll
        for (int i = 0; i < 4; i++) {
            int idx = tid + i * 256;           // 0..1023
            int r = idx >> 2, oq = idx & 3;
            float4 a = src[idx];
            __half2 h01 = __floats2half2_rn(a.x, a.y);
            __half2 h23 = __floats2half2_rn(a.z, a.w);
            uint2 u;
            u.x = *(uint32_t*)&h01;
            u.y = *(uint32_t*)&h23;
            *(uint2*)(smem + OFF_ASH + r * 48 + oq * 8) = u;
        }
    }

    // Prologue: fill chunk 0 into stage 0
    #pragma unroll
    for (int i = 0; i < 4; i++)
        cp16(sb + cpdst + i * (32 * PITCH), xsrc + i * ROWSTEP);
    #pragma unroll
    for (int i = 0; i < 8; i++)
        cp16(sb + A_TILE + cpdst + i * (32 * PITCH), ysrc + i * ROWSTEP);
    CP_COMMIT();

    float acc[4][8][4];
    #pragma unroll
    for (int mt = 0; mt < 4; mt++)
        #pragma unroll
        for (int nt = 0; nt < 8; nt++)
            #pragma unroll
            for (int q = 0; q < 4; q++) acc[mt][nt][q] = 0.0f;

    uint32_t af[2][4][4], bf[2][4][4];

    #pragma unroll 2
    for (int c = 0; c < KCHUNKS; c++) {
        CP_WAIT(0);          // chunk c landed
        __syncthreads();     // visible to all warps; other stage free

        // Prefetch chunk c+1 into the other stage
        if (c + 1 < KCHUNKS) {
            const uint32_t nstb = (uint32_t)((c + 1) & 1) * STAGE_BYTES;
            const int kb = (c + 1) * KT;
            #pragma unroll
            for (int i = 0; i < 4; i++)
                cp16(sb + nstb + cpdst + i * (32 * PITCH),
                     xsrc + i * ROWSTEP + kb);
            #pragma unroll
            for (int i = 0; i < 8; i++)
                cp16(sb + nstb + A_TILE + cpdst + i * (32 * PITCH),
                     ysrc + i * ROWSTEP + kb);
        }
        CP_COMMIT();

        const uint32_t stb = (uint32_t)(c & 1) * STAGE_BYTES;

        // Load ks=0 fragments
        #pragma unroll
        for (int mt = 0; mt < 4; mt++)
            LDMX4(af[0][mt], sb + stb + aoff + mt * (16 * PITCH));
        #pragma unroll
        for (int nb = 0; nb < 4; nb++)
            LDMX4(bf[0][nb], sb + stb + boff + nb * (16 * PITCH));

        #pragma unroll
        for (int ks = 0; ks < 4; ks++) {
            const int cur = ks & 1;
            if (ks < 3) {
                const int nxt = cur ^ 1;
                #pragma unroll
                for (int mt = 0; mt < 4; mt++)
                    LDMX4(af[nxt][mt],
                          sb + stb + aoff + mt * (16 * PITCH) + (ks + 1) * 32);
                #pragma unroll
                for (int nb = 0; nb < 4; nb++)
                    LDMX4(bf[nxt][nb],
                          sb + stb + boff + nb * (16 * PITCH) + (ks + 1) * 32);
            }
            #pragma unroll
            for (int mt = 0; mt < 4; mt++)
                #pragma unroll
                for (int nt = 0; nt < 8; nt++)
                    MMAF16(acc[mt][nt], af[cur][mt],
                           bf[cur][nt >> 1][(nt & 1) * 2],
                           bf[cur][nt >> 1][(nt & 1) * 2 + 1]);
        }
    }

    // ---------------- Epilogue ---------------------------------------------
    // W' = exp(2*gamma*C) - 1 -> fp16 Ws[128][WS_PITCH]; out += xs*(W'@alpha)
    __syncthreads();   // all LDSM done before overwriting stage region

    #pragma unroll
    for (int mt = 0; mt < 4; mt++) {
        const int m = warp_m * 64 + mt * 16 + (lane >> 2);
        #pragma unroll
        for (int nt = 0; nt < 8; nt++) {
            const int n = warp_n * 64 + nt * 8 + 2 * (lane & 3);
            float w0 = __expf(acc[mt][nt][0] * (2.0f * GAMMA)) - 1.0f;
            float w1 = __expf(acc[mt][nt][1] * (2.0f * GAMMA)) - 1.0f;
            float w2 = __expf(acc[mt][nt][2] * (2.0f * GAMMA)) - 1.0f;
            float w3 = __expf(acc[mt][nt][3] * (2.0f * GAMMA)) - 1.0f;
            *(__half2*)(smem + m * WS_PITCH + n * 2)       = __floats2half2_rn(w0, w1);
            *(__half2*)(smem + (m + 8) * WS_PITCH + n * 2) = __floats2half2_rn(w2, w3);
        }
    }
    __syncthreads();

    // Tensor GEMV: warp w handles rows [16w, 16w+16), all 16 outputs; K=256.
    float oa[2][4];
    #pragma unroll
    for (int b = 0; b < 2; b++)
        #pragma unroll
        for (int q = 0; q < 4; q++) oa[b][q] = 0.0f;

    #pragma unroll
    for (int kt = 0; kt < 16; kt++) {
        uint32_t bfr[4], afr[4];
        LDMX4T(bfr, sb + OFF_ASH + (uint32_t)(kt * 16 + (lane & 15)) * 48
                    + (uint32_t)(lane >> 4) * 16);
        LDMX4(afr, sb + (uint32_t)(wid * 16 + (lane & 15)) * WS_PITCH
                   + (uint32_t)(lane >> 4) * 16 + kt * 32);
        MMAF16(oa[0], afr, bfr[0], bfr[1]);
        MMAF16(oa[1], afr, bfr[2], bfr[3]);
    }

    {
        const int r = row0 + wid * 16 + (lane >> 2);
        const float xs0 = g_xs[r];
        const float xs1 = g_xs[r + 8];
        #pragma unroll
        for (int nt2 = 0; nt2 < 2; nt2++) {
            const int cc = nt2 * 8 + 2 * (lane & 3);
            atomicAdd(&out[(size_t)r * NOUT + cc],           oa[nt2][0] * xs0);
            atomicAdd(&out[(size_t)r * NOUT + cc + 1],       oa[nt2][1] * xs0);
            atomicAdd(&out[(size_t)(r + 8) * NOUT + cc],     oa[nt2][2] * xs1);
            atomicAdd(&out[(size_t)(r + 8) * NOUT + cc + 1], oa[nt2][3] * xs1);
        }
    }
}

// ---------------------------------------------------------------------------
extern "C" void kernel_launch(void* const* d_in, const int* in_sizes, int n_in,
                              void* d_out, int out_size) {
    const float* X     = (const float*)d_in[0];
    const float* TX    = (const float*)d_in[1];
    const float* alpha = (const float*)d_in[2];
    float* out = (float*)d_out;

    cudaFuncSetAttribute(rbf_hmma_kernel,
                         cudaFuncAttributeMaxDynamicSharedMemorySize, SMEM_BYTES);

    zero_s_kernel<<<1, 32>>>();
    prep_kernel<<<NTEST + NTRAIN, 128>>>(X, TX, alpha);
    init_out_kernel<<<(NTEST * NOUT) / 256, 256>>>(out);
    rbf_hmma_kernel<<<dim3(NTEST / BM, NTRAIN / BN), 256, SMEM_BYTES>>>(out);
}

// round 10
// speedup vs baseline: 1.1634x; 1.1634x over previous
#include <cuda_runtime.h>
#include <cuda_fp16.h>
#include <stdint.h>

// Problem constants
#define GAMMA   0.001f
#define DIM     512
#define NTEST   8192
#define NTRAIN  8192
#define NOUT    16

// Tiling
#define BM      128
#define BN      128
#define KT      64                  // fp16 K per chunk
#define KCHUNKS (DIM / KT)          // 8
#define NSTAGE  3

// SMEM: swizzled tiles, 128B pitch, no padding.
// stage = A(128 x 128B) + B(128 x 128B) = 32768B, 3 stages.
#define TILE_B      16384
#define STAGE_BYTES 32768
#define OFF_ASH     (NSTAGE * STAGE_BYTES)   // 98304: alpha fp16 128 x 48B
#define SMEM_BYTES  (OFF_ASH + 6144)         // 104448 -> 2 CTAs/SM
#define WS_PITCH    272                      // fp16 W' epilogue pitch

// Device scratch
__device__ __half g_Xh[NTEST * DIM];
__device__ __half g_Yh[NTRAIN * DIM];
__device__ float  g_xs[NTEST];           // exp(-gamma*||x||^2)
__device__ float  g_as[NTRAIN * NOUT];   // alpha * exp(-gamma*||y||^2)
__device__ float  g_S[NOUT];             // column sums of g_as

// ---------------------------------------------------------------------------
__device__ __forceinline__ uint32_t smem_u32(const void* p) {
    uint32_t a;
    asm("{ .reg .u64 t; cvta.to.shared.u64 t, %1; cvt.u32.u64 %0, t; }"
        : "=r"(a) : "l"(p));
    return a;
}
__device__ __forceinline__ void cp16(uint32_t dst, const void* src) {
    asm volatile("cp.async.cg.shared.global [%0], [%1], 16;"
                 :: "r"(dst), "l"(src));
}
#define CP_COMMIT() asm volatile("cp.async.commit_group;" ::: "memory")
#define CP_WAIT(n)  asm volatile("cp.async.wait_group %0;" :: "n"(n) : "memory")

#define LDMX4(r, addr) \
    asm volatile("ldmatrix.sync.aligned.m8n8.x4.shared.b16 {%0,%1,%2,%3}, [%4];" \
        : "=r"((r)[0]), "=r"((r)[1]), "=r"((r)[2]), "=r"((r)[3]) : "r"(addr))

#define LDMX4T(r, addr) \
    asm volatile("ldmatrix.sync.aligned.m8n8.x4.trans.shared.b16 {%0,%1,%2,%3}, [%4];" \
        : "=r"((r)[0]), "=r"((r)[1]), "=r"((r)[2]), "=r"((r)[3]) : "r"(addr))

#define MMAF16(c, a, b0, b1) \
    asm volatile("mma.sync.aligned.m16n8k16.row.col.f32.f16.f16.f32 " \
        "{%0,%1,%2,%3}, {%4,%5,%6,%7}, {%8,%9}, {%0,%1,%2,%3};" \
        : "+f"((c)[0]), "+f"((c)[1]), "+f"((c)[2]), "+f"((c)[3]) \
        : "r"((a)[0]), "r"((a)[1]), "r"((a)[2]), "r"((a)[3]), "r"(b0), "r"(b1))

// ---------------------------------------------------------------------------
__global__ void zero_s_kernel() {
    if (threadIdx.x < NOUT) g_S[threadIdx.x] = 0.0f;
}

// Prep: fp32 -> fp16 + norm folding + global alpha column sums.
__global__ void prep_kernel(const float* __restrict__ X,
                            const float* __restrict__ TX,
                            const float* __restrict__ alpha) {
    const int row = blockIdx.x;
    const bool train = (row >= NTEST);
    const int r = train ? row - NTEST : row;
    const float* src = train ? TX + (size_t)r * DIM : X + (size_t)r * DIM;
    __half* dst = train ? g_Yh + (size_t)r * DIM : g_Xh + (size_t)r * DIM;

    float4 v = ((const float4*)src)[threadIdx.x];
    __half2* d2 = (__half2*)dst;
    d2[threadIdx.x * 2]     = __floats2half2_rn(v.x, v.y);
    d2[threadIdx.x * 2 + 1] = __floats2half2_rn(v.z, v.w);

    float s = v.x * v.x + v.y * v.y + v.z * v.z + v.w * v.w;
    #pragma unroll
    for (int off = 16; off > 0; off >>= 1)
        s += __shfl_down_sync(0xffffffffu, s, off);
    __shared__ float red[4];
    if ((threadIdx.x & 31) == 0) red[threadIdx.x >> 5] = s;
    __syncthreads();
    if (threadIdx.x < NOUT) {
        float e = __expf(-GAMMA * (red[0] + red[1] + red[2] + red[3]));
        if (train) {
            float val = alpha[r * NOUT + threadIdx.x] * e;
            g_as[r * NOUT + threadIdx.x] = val;
            atomicAdd(&g_S[threadIdx.x], val);
        } else if (threadIdx.x == 0) {
            g_xs[r] = e;
        }
    }
}

// Init: out[r][o] = xs[r] * S[o]   (the "+1" part of W = 1 + w')
__global__ void init_out_kernel(float* __restrict__ out) {
    int i = blockIdx.x * 256 + threadIdx.x;
    out[i] = g_xs[i >> 4] * g_S[i & 15];
}

// ---------------------------------------------------------------------------
// Main: 128x128 fp16 HMMA GEMM (K=512), KT=64, 3-stage swizzled cp.async
// (prefetch distance 2), fragment double buffering; fp16 HMMA epilogue.
// 4 warps (2x2), warp tile 64x64, 2 CTAs/SM.
// ---------------------------------------------------------------------------
__global__ __launch_bounds__(128, 2)
void rbf_hmma_kernel(float* __restrict__ out) {
    extern __shared__ __align__(1024) uint8_t smem[];
    const uint32_t sb = smem_u32(smem);

    const int tid    = threadIdx.x;
    const int lane   = tid & 31;
    const int wid    = tid >> 5;
    const int warp_m = wid & 1;
    const int warp_n = wid >> 1;
    const int row0   = blockIdx.x * BM;
    const int j0     = blockIdx.y * BN;

    // ldmatrix lane geometry (swizzled 128B-pitch tiles)
    const int arow = warp_m * 64 + ((lane >> 3) & 1) * 8 + (lane & 7);
    const int ahi  = lane >> 4;            // col16 sub-offset 0/1
    const int ax7  = arow & 7;
    const uint32_t arowb = (uint32_t)arow * 128;

    const int brow = warp_n * 64 + ((lane >> 4) & 1) * 8 + (lane & 7);
    const int bhi  = (lane >> 3) & 1;
    const int bx7  = brow & 7;
    const uint32_t browb = TILE_B + (uint32_t)brow * 128;

    // cp.async: thread -> (row tid>>3, granule tid&7), swizzled dst
    const int cprow = tid >> 3;          // 0..15
    const int cpkg  = tid & 7;
    const __half* xsrc = g_Xh + (size_t)(row0 + cprow) * DIM + cpkg * 8;
    const __half* ysrc = g_Yh + (size_t)(j0   + cprow) * DIM + cpkg * 8;
    const uint32_t cpdst = (uint32_t)cprow * 128
                         + (uint32_t)((cpkg ^ (cprow & 7)) << 4);
    const uint32_t ROWSTEP = 16 * DIM;   // elements per +16 rows

    // Stage the scaled-alpha tile as fp16 [128 rows][48B pitch]
    {
        const float4* src = (const float4*)(g_as + (size_t)j0 * NOUT);
        #pragma unroll
        for (int i = 0; i < 4; i++) {
            int idx = tid + i * 128;
            int r = idx >> 2, oq = idx & 3;
            float4 a = src[idx];
            __half2 h01 = __floats2half2_rn(a.x, a.y);
            __half2 h23 = __floats2half2_rn(a.z, a.w);
            uint2 u;
            u.x = *(uint32_t*)&h01;
            u.y = *(uint32_t*)&h23;
            *(uint2*)(smem + OFF_ASH + r * 48 + oq * 8) = u;
        }
    }

    // Prologue: chunks 0,1 -> stages 0,1
    #pragma unroll
    for (int p = 0; p < 2; p++) {
        const uint32_t stb = (uint32_t)p * STAGE_BYTES;
        #pragma unroll
        for (int i = 0; i < 8; i++) {
            cp16(sb + stb + cpdst + i * 2048,          xsrc + i * ROWSTEP + p * KT);
            cp16(sb + stb + TILE_B + cpdst + i * 2048, ysrc + i * ROWSTEP + p * KT);
        }
        CP_COMMIT();
    }

    float acc[4][8][4];
    #pragma unroll
    for (int mt = 0; mt < 4; mt++)
        #pragma unroll
        for (int nt = 0; nt < 8; nt++)
            #pragma unroll
            for (int q = 0; q < 4; q++) acc[mt][nt][q] = 0.0f;

    uint32_t af[2][4][4], bf[2][4][4];

    for (int c = 0; c < KCHUNKS; c++) {
        CP_WAIT(1);          // chunk c landed (c+1 may still be in flight)
        __syncthreads();     // all warps done with stage (c+2)%3's old data

        // Prefetch chunk c+2 into stage (c+2)%3  (distance-2)
        if (c + 2 < KCHUNKS) {
            const uint32_t nstb = (uint32_t)((c + 2) % 3) * STAGE_BYTES;
            const int kb = (c + 2) * KT;
            #pragma unroll
            for (int i = 0; i < 8; i++) {
                cp16(sb + nstb + cpdst + i * 2048,
                     xsrc + i * ROWSTEP + kb);
                cp16(sb + nstb + TILE_B + cpdst + i * 2048,
                     ysrc + i * ROWSTEP + kb);
            }
        }
        CP_COMMIT();         // empty group at tail keeps CP_WAIT(1) uniform

        const uint32_t stb = (uint32_t)(c % 3) * STAGE_BYTES;

        // Load ks=0 fragments (swizzled column offsets)
        {
            const uint32_t acol = (uint32_t)((ahi ^ ax7) << 4);
            const uint32_t bcol = (uint32_t)((bhi ^ bx7) << 4);
            #pragma unroll
            for (int mt = 0; mt < 4; mt++)
                LDMX4(af[0][mt], sb + stb + arowb + mt * 2048 + acol);
            #pragma unroll
            for (int nb = 0; nb < 4; nb++)
                LDMX4(bf[0][nb], sb + stb + browb + nb * 2048 + bcol);
        }

        #pragma unroll
        for (int ks = 0; ks < 4; ks++) {
            const int cur = ks & 1;
            if (ks < 3) {
                const int nxt = cur ^ 1;
                const uint32_t acol =
                    (uint32_t)(((2 * (ks + 1) + ahi) ^ ax7) << 4);
                const uint32_t bcol =
                    (uint32_t)(((2 * (ks + 1) + bhi) ^ bx7) << 4);
                #pragma unroll
                for (int mt = 0; mt < 4; mt++)
                    LDMX4(af[nxt][mt], sb + stb + arowb + mt * 2048 + acol);
                #pragma unroll
                for (int nb = 0; nb < 4; nb++)
                    LDMX4(bf[nxt][nb], sb + stb + browb + nb * 2048 + bcol);
            }
            #pragma unroll
            for (int mt = 0; mt < 4; mt++)
                #pragma unroll
                for (int nt = 0; nt < 8; nt++)
                    MMAF16(acc[mt][nt], af[cur][mt],
                           bf[cur][nt >> 1][(nt & 1) * 2],
                           bf[cur][nt >> 1][(nt & 1) * 2 + 1]);
        }
    }

    // ---------------- Epilogue ---------------------------------------------
    // W' = exp(2*gamma*C) - 1 -> fp16 Ws[128][WS_PITCH]; out += xs*(W'@alpha)
    __syncthreads();   // all LDSM done before overwriting stage region

    #pragma unroll
    for (int mt = 0; mt < 4; mt++) {
        const int m = warp_m * 64 + mt * 16 + (lane >> 2);
        #pragma unroll
        for (int nt = 0; nt < 8; nt++) {
            const int n = warp_n * 64 + nt * 8 + 2 * (lane & 3);
            float w0 = __expf(acc[mt][nt][0] * (2.0f * GAMMA)) - 1.0f;
            float w1 = __expf(acc[mt][nt][1] * (2.0f * GAMMA)) - 1.0f;
            float w2 = __expf(acc[mt][nt][2] * (2.0f * GAMMA)) - 1.0f;
            float w3 = __expf(acc[mt][nt][3] * (2.0f * GAMMA)) - 1.0f;
            *(__half2*)(smem + m * WS_PITCH + n * 2)       = __floats2half2_rn(w0, w1);
            *(__half2*)(smem + (m + 8) * WS_PITCH + n * 2) = __floats2half2_rn(w2, w3);
        }
    }
    __syncthreads();

    // Tensor GEMV: warp w handles rows [32w, 32w+32), all 16 outputs.
    float oa[2][2][4];
    #pragma unroll
    for (int a = 0; a < 2; a++)
        #pragma unroll
        for (int b = 0; b < 2; b++)
            #pragma unroll
            for (int q = 0; q < 4; q++) oa[a][b][q] = 0.0f;

    #pragma unroll
    for (int kt = 0; kt < 8; kt++) {
        uint32_t bfr[4];
        LDMX4T(bfr, sb + OFF_ASH + (uint32_t)(kt * 16 + (lane & 15)) * 48
                    + (uint32_t)(lane >> 4) * 16);
        #pragma unroll
        for (int mt2 = 0; mt2 < 2; mt2++) {
            uint32_t afr[4];
            LDMX4(afr, sb + (uint32_t)(wid * 32 + mt2 * 16 + (lane & 15)) * WS_PITCH
                       + (uint32_t)(lane >> 4) * 16 + kt * 32);
            MMAF16(oa[mt2][0], afr, bfr[0], bfr[1]);
            MMAF16(oa[mt2][1], afr, bfr[2], bfr[3]);
        }
    }

    #pragma unroll
    for (int mt2 = 0; mt2 < 2; mt2++) {
        const int r = row0 + wid * 32 + mt2 * 16 + (lane >> 2);
        const float xs0 = g_xs[r];
        const float xs1 = g_xs[r + 8];
        #pragma unroll
        for (int nt2 = 0; nt2 < 2; nt2++) {
            const int cc = nt2 * 8 + 2 * (lane & 3);
            atomicAdd(&out[(size_t)r * NOUT + cc],           oa[mt2][nt2][0] * xs0);
            atomicAdd(&out[(size_t)r * NOUT + cc + 1],       oa[mt2][nt2][1] * xs0);
            atomicAdd(&out[(size_t)(r + 8) * NOUT + cc],     oa[mt2][nt2][2] * xs1);
            atomicAdd(&out[(size_t)(r + 8) * NOUT + cc + 1], oa[mt2][nt2][3] * xs1);
        }
    }
}

// ---------------------------------------------------------------------------
extern "C" void kernel_launch(void* const* d_in, const int* in_sizes, int n_in,
                              void* d_out, int out_size) {
    const float* X     = (const float*)d_in[0];
    const float* TX    = (const float*)d_in[1];
    const float* alpha = (const float*)d_in[2];
    float* out = (float*)d_out;

    cudaFuncSetAttribute(rbf_hmma_kernel,
                         cudaFuncAttributeMaxDynamicSharedMemorySize, SMEM_BYTES);

    zero_s_kernel<<<1, 32>>>();
    prep_kernel<<<NTEST + NTRAIN, 128>>>(X, TX, alpha);
    init_out_kernel<<<(NTEST * NOUT) / 256, 256>>>(out);
    rbf_hmma_kernel<<<dim3(NTEST / BM, NTRAIN / BN), 128, SMEM_BYTES>>>(out);
}

// round 11
// speedup vs baseline: 1.2462x; 1.0712x over previous
#include <cuda_runtime.h>
#include <cuda_fp16.h>
#include <stdint.h>

// Problem constants
#define GAMMA   0.001f
#define DIM     512
#define NTEST   8192
#define NTRAIN  8192
#define NOUT    16

// Tiling
#define BM      128
#define BN      128
#define KT      64                  // fp16 K per chunk
#define KCHUNKS (DIM / KT)          // 8
#define NSTAGE  3

// SMEM: swizzled tiles, 128B pitch, no padding.
// stage = A(128 x 128B) + B(128 x 128B) = 32768B, 3 stages.
#define TILE_B      16384
#define STAGE_BYTES 32768
#define OFF_ASH     (NSTAGE * STAGE_BYTES)   // 98304: alpha fp16 128 x 48B
#define SMEM_BYTES  (OFF_ASH + 6144)         // 104448 -> 2 CTAs/SM

// Device scratch
__device__ __half g_Xh[NTEST * DIM];
__device__ __half g_Yh[NTRAIN * DIM];
__device__ float  g_xs[NTEST];           // exp(-gamma*||x||^2)
__device__ float  g_as[NTRAIN * NOUT];   // alpha * exp(-gamma*||y||^2)
__device__ float  g_S[NOUT];             // column sums of g_as

// ---------------------------------------------------------------------------
__device__ __forceinline__ uint32_t smem_u32(const void* p) {
    uint32_t a;
    asm("{ .reg .u64 t; cvta.to.shared.u64 t, %1; cvt.u32.u64 %0, t; }"
        : "=r"(a) : "l"(p));
    return a;
}
__device__ __forceinline__ void cp16(uint32_t dst, const void* src) {
    asm volatile("cp.async.cg.shared.global [%0], [%1], 16;"
                 :: "r"(dst), "l"(src));
}
#define CP_COMMIT() asm volatile("cp.async.commit_group;" ::: "memory")
#define CP_WAIT(n)  asm volatile("cp.async.wait_group %0;" :: "n"(n) : "memory")

#define LDMX4(r, addr) \
    asm volatile("ldmatrix.sync.aligned.m8n8.x4.shared.b16 {%0,%1,%2,%3}, [%4];" \
        : "=r"((r)[0]), "=r"((r)[1]), "=r"((r)[2]), "=r"((r)[3]) : "r"(addr))

#define LDMX4T(r, addr) \
    asm volatile("ldmatrix.sync.aligned.m8n8.x4.trans.shared.b16 {%0,%1,%2,%3}, [%4];" \
        : "=r"((r)[0]), "=r"((r)[1]), "=r"((r)[2]), "=r"((r)[3]) : "r"(addr))

#define MMAF16(c, a, b0, b1) \
    asm volatile("mma.sync.aligned.m16n8k16.row.col.f32.f16.f16.f32 " \
        "{%0,%1,%2,%3}, {%4,%5,%6,%7}, {%8,%9}, {%0,%1,%2,%3};" \
        : "+f"((c)[0]), "+f"((c)[1]), "+f"((c)[2]), "+f"((c)[3]) \
        : "r"((a)[0]), "r"((a)[1]), "r"((a)[2]), "r"((a)[3]), "r"(b0), "r"(b1))

// ---------------------------------------------------------------------------
__global__ void zero_s_kernel() {
    if (threadIdx.x < NOUT) g_S[threadIdx.x] = 0.0f;
}

// Prep: fp32 -> fp16 + norm folding + global alpha column sums.
__global__ void prep_kernel(const float* __restrict__ X,
                            const float* __restrict__ TX,
                            const float* __restrict__ alpha) {
    const int row = blockIdx.x;
    const bool train = (row >= NTEST);
    const int r = train ? row - NTEST : row;
    const float* src = train ? TX + (size_t)r * DIM : X + (size_t)r * DIM;
    __half* dst = train ? g_Yh + (size_t)r * DIM : g_Xh + (size_t)r * DIM;

    float4 v = ((const float4*)src)[threadIdx.x];
    __half2* d2 = (__half2*)dst;
    d2[threadIdx.x * 2]     = __floats2half2_rn(v.x, v.y);
    d2[threadIdx.x * 2 + 1] = __floats2half2_rn(v.z, v.w);

    float s = v.x * v.x + v.y * v.y + v.z * v.z + v.w * v.w;
    #pragma unroll
    for (int off = 16; off > 0; off >>= 1)
        s += __shfl_down_sync(0xffffffffu, s, off);
    __shared__ float red[4];
    if ((threadIdx.x & 31) == 0) red[threadIdx.x >> 5] = s;
    __syncthreads();
    if (threadIdx.x < NOUT) {
        float e = __expf(-GAMMA * (red[0] + red[1] + red[2] + red[3]));
        if (train) {
            float val = alpha[r * NOUT + threadIdx.x] * e;
            g_as[r * NOUT + threadIdx.x] = val;
            atomicAdd(&g_S[threadIdx.x], val);
        } else if (threadIdx.x == 0) {
            g_xs[r] = e;
        }
    }
}

// Init: out[r][o] = xs[r] * S[o]   (the "+1" part of W = 1 + w')
__global__ void init_out_kernel(float* __restrict__ out) {
    int i = blockIdx.x * 256 + threadIdx.x;
    out[i] = g_xs[i >> 4] * g_S[i & 15];
}

// ---------------------------------------------------------------------------
// Main: 128x128 fp16 HMMA GEMM (K=512), KT=64, 3-stage swizzled cp.async
// (prefetch distance 2), fragment double buffering.
// Epilogue: exp(2g c)-1 converted to fp16 A-fragments IN REGISTERS, MMA'd
// against alpha B-fragments; per-warp partial outputs merged via atomicAdd.
// 4 warps (2x2), warp tile 64x64, 2 CTAs/SM.
// ---------------------------------------------------------------------------
__global__ __launch_bounds__(128, 2)
void rbf_hmma_kernel(float* __restrict__ out) {
    extern __shared__ __align__(1024) uint8_t smem[];
    const uint32_t sb = smem_u32(smem);

    const int tid    = threadIdx.x;
    const int lane   = tid & 31;
    const int wid    = tid >> 5;
    const int warp_m = wid & 1;
    const int warp_n = wid >> 1;
    const int row0   = blockIdx.x * BM;
    const int j0     = blockIdx.y * BN;

    // ldmatrix lane geometry (swizzled 128B-pitch tiles)
    const int arow = warp_m * 64 + ((lane >> 3) & 1) * 8 + (lane & 7);
    const int ahi  = lane >> 4;
    const int ax7  = arow & 7;
    const uint32_t arowb = (uint32_t)arow * 128;

    const int brow = warp_n * 64 + ((lane >> 4) & 1) * 8 + (lane & 7);
    const int bhi  = (lane >> 3) & 1;
    const int bx7  = brow & 7;
    const uint32_t browb = TILE_B + (uint32_t)brow * 128;

    // Precomputed swizzled column offsets for ks = 0..3
    uint32_t acolv[4], bcolv[4];
    #pragma unroll
    for (int ks = 0; ks < 4; ks++) {
        acolv[ks] = (uint32_t)(((2 * ks + ahi) ^ ax7) << 4);
        bcolv[ks] = (uint32_t)(((2 * ks + bhi) ^ bx7) << 4);
    }

    // cp.async: thread -> (row tid>>3, granule tid&7), swizzled dst
    const int cprow = tid >> 3;
    const int cpkg  = tid & 7;
    const __half* xsrc = g_Xh + (size_t)(row0 + cprow) * DIM + cpkg * 8;
    const __half* ysrc = g_Yh + (size_t)(j0   + cprow) * DIM + cpkg * 8;
    const uint32_t cpdst = (uint32_t)cprow * 128
                         + (uint32_t)((cpkg ^ (cprow & 7)) << 4);
    const uint32_t ROWSTEP = 16 * DIM;

    // Stage the scaled-alpha tile as fp16 [128 rows][48B pitch]
    {
        const float4* src = (const float4*)(g_as + (size_t)j0 * NOUT);
        #pragma unroll
        for (int i = 0; i < 4; i++) {
            int idx = tid + i * 128;
            int r = idx >> 2, oq = idx & 3;
            float4 a = src[idx];
            __half2 h01 = __floats2half2_rn(a.x, a.y);
            __half2 h23 = __floats2half2_rn(a.z, a.w);
            uint2 u;
            u.x = *(uint32_t*)&h01;
            u.y = *(uint32_t*)&h23;
            *(uint2*)(smem + OFF_ASH + r * 48 + oq * 8) = u;
        }
    }

    // Prologue: chunks 0,1 -> stages 0,1
    #pragma unroll
    for (int p = 0; p < 2; p++) {
        const uint32_t stb = (uint32_t)p * STAGE_BYTES;
        #pragma unroll
        for (int i = 0; i < 8; i++) {
            cp16(sb + stb + cpdst + i * 2048,          xsrc + i * ROWSTEP + p * KT);
            cp16(sb + stb + TILE_B + cpdst + i * 2048, ysrc + i * ROWSTEP + p * KT);
        }
        CP_COMMIT();
    }

    float acc[4][8][4];
    #pragma unroll
    for (int mt = 0; mt < 4; mt++)
        #pragma unroll
        for (int nt = 0; nt < 8; nt++)
            #pragma unroll
            for (int q = 0; q < 4; q++) acc[mt][nt][q] = 0.0f;

    uint32_t af[2][4][4], bf[2][4][4];

    for (int c = 0; c < KCHUNKS; c++) {
        CP_WAIT(1);          // chunk c landed (c+1 may still be in flight)
        __syncthreads();     // all warps done with stage (c+2)%3's old data

        const uint32_t stb = (uint32_t)(c % 3) * STAGE_BYTES;

        // Critical path first: load ks=0 fragments
        #pragma unroll
        for (int mt = 0; mt < 4; mt++)
            LDMX4(af[0][mt], sb + stb + arowb + mt * 2048 + acolv[0]);
        #pragma unroll
        for (int nb = 0; nb < 4; nb++)
            LDMX4(bf[0][nb], sb + stb + browb + nb * 2048 + bcolv[0]);

        // Then issue prefetch of chunk c+2 into stage (c+2)%3
        if (c + 2 < KCHUNKS) {
            const uint32_t nstb = (uint32_t)((c + 2) % 3) * STAGE_BYTES;
            const int kb = (c + 2) * KT;
            #pragma unroll
            for (int i = 0; i < 8; i++) {
                cp16(sb + nstb + cpdst + i * 2048,
                     xsrc + i * ROWSTEP + kb);
                cp16(sb + nstb + TILE_B + cpdst + i * 2048,
                     ysrc + i * ROWSTEP + kb);
            }
        }
        CP_COMMIT();         // empty group at tail keeps CP_WAIT(1) uniform

        #pragma unroll
        for (int ks = 0; ks < 4; ks++) {
            const int cur = ks & 1;
            if (ks < 3) {
                const int nxt = cur ^ 1;
                #pragma unroll
                for (int mt = 0; mt < 4; mt++)
                    LDMX4(af[nxt][mt],
                          sb + stb + arowb + mt * 2048 + acolv[ks + 1]);
                #pragma unroll
                for (int nb = 0; nb < 4; nb++)
                    LDMX4(bf[nxt][nb],
                          sb + stb + browb + nb * 2048 + bcolv[ks + 1]);
            }
            #pragma unroll
            for (int mt = 0; mt < 4; mt++)
                #pragma unroll
                for (int nt = 0; nt < 8; nt++)
                    MMAF16(acc[mt][nt], af[cur][mt],
                           bf[cur][nt >> 1][(nt & 1) * 2],
                           bf[cur][nt >> 1][(nt & 1) * 2 + 1]);
        }
    }

    // ---------------- Epilogue (register-direct) ----------------------------
    // W' = exp(2*gamma*C) - 1 -> fp16 A-fragments straight from acc;
    // O_partial = W'(warp's 64-col k-slice) @ alpha -> atomicAdd.
    // No smem staging, no barriers.
    float oa[4][2][4];
    #pragma unroll
    for (int mt = 0; mt < 4; mt++)
        #pragma unroll
        for (int b = 0; b < 2; b++)
            #pragma unroll
            for (int q = 0; q < 4; q++) oa[mt][b][q] = 0.0f;

    #pragma unroll
    for (int kt = 0; kt < 4; kt++) {          // k-tile within warp's 64 cols
        const int ktg = warp_n * 4 + kt;      // global 16-col tile index
        uint32_t bfr[4];
        LDMX4T(bfr, sb + OFF_ASH + (uint32_t)(ktg * 16 + (lane & 15)) * 48
                    + (uint32_t)(lane >> 4) * 16);
        #pragma unroll
        for (int mt = 0; mt < 4; mt++) {
            const float* c0 = acc[mt][2 * kt];
            const float* c1 = acc[mt][2 * kt + 1];
            __half2 h0 = __floats2half2_rn(
                __expf(c0[0] * (2.0f * GAMMA)) - 1.0f,
                __expf(c0[1] * (2.0f * GAMMA)) - 1.0f);
            __half2 h1 = __floats2half2_rn(
                __expf(c0[2] * (2.0f * GAMMA)) - 1.0f,
                __expf(c0[3] * (2.0f * GAMMA)) - 1.0f);
            __half2 h2 = __floats2half2_rn(
                __expf(c1[0] * (2.0f * GAMMA)) - 1.0f,
                __expf(c1[1] * (2.0f * GAMMA)) - 1.0f);
            __half2 h3 = __floats2half2_rn(
                __expf(c1[2] * (2.0f * GAMMA)) - 1.0f,
                __expf(c1[3] * (2.0f * GAMMA)) - 1.0f);
            uint32_t afr[4];
            afr[0] = *(uint32_t*)&h0;   // (row,   k, k+1)
            afr[1] = *(uint32_t*)&h1;   // (row+8, k, k+1)
            afr[2] = *(uint32_t*)&h2;   // (row,   k+8, k+9)
            afr[3] = *(uint32_t*)&h3;   // (row+8, k+8, k+9)
            MMAF16(oa[mt][0], afr, bfr[0], bfr[1]);
            MMAF16(oa[mt][1], afr, bfr[2], bfr[3]);
        }
    }

    #pragma unroll
    for (int mt = 0; mt < 4; mt++) {
        const int r = row0 + warp_m * 64 + mt * 16 + (lane >> 2);
        const float xs0 = g_xs[r];
        const float xs1 = g_xs[r + 8];
        #pragma unroll
        for (int b = 0; b < 2; b++) {
            const int cc = b * 8 + 2 * (lane & 3);
            atomicAdd(&out[(size_t)r * NOUT + cc],           oa[mt][b][0] * xs0);
            atomicAdd(&out[(size_t)r * NOUT + cc + 1],       oa[mt][b][1] * xs0);
            atomicAdd(&out[(size_t)(r + 8) * NOUT + cc],     oa[mt][b][2] * xs1);
            atomicAdd(&out[(size_t)(r + 8) * NOUT + cc + 1], oa[mt][b][3] * xs1);
        }
    }
}

// ---------------------------------------------------------------------------
extern "C" void kernel_launch(void* const* d_in, const int* in_sizes, int n_in,
                              void* d_out, int out_size) {
    const float* X     = (const float*)d_in[0];
    const float* TX    = (const float*)d_in[1];
    const float* alpha = (const float*)d_in[2];
    float* out = (float*)d_out;

    cudaFuncSetAttribute(rbf_hmma_kernel,
                         cudaFuncAttributeMaxDynamicSharedMemorySize, SMEM_BYTES);

    zero_s_kernel<<<1, 32>>>();
    prep_kernel<<<NTEST + NTRAIN, 128>>>(X, TX, alpha);
    init_out_kernel<<<(NTEST * NOUT) / 256, 256>>>(out);
    rbf_hmma_kernel<<<dim3(NTEST / BM, NTRAIN / BN), 128, SMEM_BYTES>>>(out);
}

// round 12
// speedup vs baseline: 1.3745x; 1.1030x over previous
#include <cuda_runtime.h>
#include <cuda_fp16.h>
#include <stdint.h>

// Problem constants
#define GAMMA   0.001f
#define DIM     512
#define NTEST   8192
#define NTRAIN  8192
#define NOUT    16

// Tiling
#define BM      128
#define BN      128
#define KT      64                  // fp16 K per chunk
#define KCHUNKS (DIM / KT)          // 8
#define NSTAGE  3

// SMEM: swizzled tiles, 128B pitch, no padding.
#define TILE_B      16384
#define STAGE_BYTES 32768
#define OFF_ASH     (NSTAGE * STAGE_BYTES)   // 98304: alpha fp16 128 x 48B
#define SMEM_BYTES  (OFF_ASH + 6144)         // 104448 -> 2 CTAs/SM

// Device scratch
__device__ __half g_Xh[NTEST * DIM];
__device__ __half g_Yh[NTRAIN * DIM];
__device__ float  g_xs[NTEST];           // exp(-gamma*||x||^2)
__device__ float  g_as[NTRAIN * NOUT];   // alpha * exp(-gamma*||y||^2)
__device__ float  g_S[NOUT];             // column sums of g_as

// ---------------------------------------------------------------------------
__device__ __forceinline__ uint32_t smem_u32(const void* p) {
    uint32_t a;
    asm("{ .reg .u64 t; cvta.to.shared.u64 t, %1; cvt.u32.u64 %0, t; }"
        : "=r"(a) : "l"(p));
    return a;
}
__device__ __forceinline__ void cp16(uint32_t dst, const void* src) {
    asm volatile("cp.async.cg.shared.global [%0], [%1], 16;"
                 :: "r"(dst), "l"(src));
}
#define CP_COMMIT() asm volatile("cp.async.commit_group;" ::: "memory")
#define CP_WAIT(n)  asm volatile("cp.async.wait_group %0;" :: "n"(n) : "memory")

#define LDMX4(r, addr) \
    asm volatile("ldmatrix.sync.aligned.m8n8.x4.shared.b16 {%0,%1,%2,%3}, [%4];" \
        : "=r"((r)[0]), "=r"((r)[1]), "=r"((r)[2]), "=r"((r)[3]) : "r"(addr))

#define LDMX4T(r, addr) \
    asm volatile("ldmatrix.sync.aligned.m8n8.x4.trans.shared.b16 {%0,%1,%2,%3}, [%4];" \
        : "=r"((r)[0]), "=r"((r)[1]), "=r"((r)[2]), "=r"((r)[3]) : "r"(addr))

#define MMAF16(c, a, b0, b1) \
    asm volatile("mma.sync.aligned.m16n8k16.row.col.f32.f16.f16.f32 " \
        "{%0,%1,%2,%3}, {%4,%5,%6,%7}, {%8,%9}, {%0,%1,%2,%3};" \
        : "+f"((c)[0]), "+f"((c)[1]), "+f"((c)[2]), "+f"((c)[3]) \
        : "r"((a)[0]), "r"((a)[1]), "r"((a)[2]), "r"((a)[3]), "r"(b0), "r"(b1))

// ---------------------------------------------------------------------------
__global__ void zero_s_kernel() {
    if (threadIdx.x < NOUT) g_S[threadIdx.x] = 0.0f;
}

// Prep: fp32 -> fp16 + norm folding + global alpha column sums.
__global__ void prep_kernel(const float* __restrict__ X,
                            const float* __restrict__ TX,
                            const float* __restrict__ alpha) {
    const int row = blockIdx.x;
    const bool train = (row >= NTEST);
    const int r = train ? row - NTEST : row;
    const float* src = train ? TX + (size_t)r * DIM : X + (size_t)r * DIM;
    __half* dst = train ? g_Yh + (size_t)r * DIM : g_Xh + (size_t)r * DIM;

    float4 v = ((const float4*)src)[threadIdx.x];
    __half2* d2 = (__half2*)dst;
    d2[threadIdx.x * 2]     = __floats2half2_rn(v.x, v.y);
    d2[threadIdx.x * 2 + 1] = __floats2half2_rn(v.z, v.w);

    float s = v.x * v.x + v.y * v.y + v.z * v.z + v.w * v.w;
    #pragma unroll
    for (int off = 16; off > 0; off >>= 1)
        s += __shfl_down_sync(0xffffffffu, s, off);
    __shared__ float red[4];
    if ((threadIdx.x & 31) == 0) red[threadIdx.x >> 5] = s;
    __syncthreads();
    if (threadIdx.x < NOUT) {
        float e = __expf(-GAMMA * (red[0] + red[1] + red[2] + red[3]));
        if (train) {
            float val = alpha[r * NOUT + threadIdx.x] * e;
            g_as[r * NOUT + threadIdx.x] = val;
            atomicAdd(&g_S[threadIdx.x], val);
        } else if (threadIdx.x == 0) {
            g_xs[r] = e;
        }
    }
}

// Init: out[r][o] = xs[r] * S[o]   (the "+1" part of W = 1 + w')
__global__ void init_out_kernel(float* __restrict__ out) {
    int i = blockIdx.x * 256 + threadIdx.x;
    out[i] = g_xs[i >> 4] * g_S[i & 15];
}

// ---------------------------------------------------------------------------
// Main: 128x128 fp16 HMMA GEMM (K=512), KT=64, 3-stage swizzled cp.async,
// cross-chunk fragment prefetch (barrier inside ks=3), fully unrolled.
// Epilogue: register-direct exp->fp16 A-frags, HMMA vs alpha, atomicAdd.
// 4 warps (2x2), warp tile 64x64, 2 CTAs/SM.
// ---------------------------------------------------------------------------
__global__ __launch_bounds__(128, 2)
void rbf_hmma_kernel(float* __restrict__ out) {
    extern __shared__ __align__(1024) uint8_t smem[];
    const uint32_t sb = smem_u32(smem);

    const int tid    = threadIdx.x;
    const int lane   = tid & 31;
    const int wid    = tid >> 5;
    const int warp_m = wid & 1;
    const int warp_n = wid >> 1;
    const int row0   = blockIdx.x * BM;
    const int j0     = blockIdx.y * BN;

    // ldmatrix lane geometry (swizzled 128B-pitch tiles)
    const int arow = warp_m * 64 + ((lane >> 3) & 1) * 8 + (lane & 7);
    const int ahi  = lane >> 4;
    const int ax7  = arow & 7;
    const uint32_t arowb = (uint32_t)arow * 128;

    const int brow = warp_n * 64 + ((lane >> 4) & 1) * 8 + (lane & 7);
    const int bhi  = (lane >> 3) & 1;
    const int bx7  = brow & 7;
    const uint32_t browb = TILE_B + (uint32_t)brow * 128;

    // Precomputed swizzled column offsets for ks = 0..3
    uint32_t acolv[4], bcolv[4];
    #pragma unroll
    for (int ks = 0; ks < 4; ks++) {
        acolv[ks] = (uint32_t)(((2 * ks + ahi) ^ ax7) << 4);
        bcolv[ks] = (uint32_t)(((2 * ks + bhi) ^ bx7) << 4);
    }

    // cp.async: thread -> (row tid>>3, granule tid&7), swizzled dst
    const int cprow = tid >> 3;
    const int cpkg  = tid & 7;
    const __half* xsrc = g_Xh + (size_t)(row0 + cprow) * DIM + cpkg * 8;
    const __half* ysrc = g_Yh + (size_t)(j0   + cprow) * DIM + cpkg * 8;
    const uint32_t cpdst = (uint32_t)cprow * 128
                         + (uint32_t)((cpkg ^ (cprow & 7)) << 4);
    const uint32_t ROWSTEP = 16 * DIM;

    // Stage the scaled-alpha tile as fp16 [128 rows][48B pitch]
    {
        const float4* src = (const float4*)(g_as + (size_t)j0 * NOUT);
        #pragma unroll
        for (int i = 0; i < 4; i++) {
            int idx = tid + i * 128;
            int r = idx >> 2, oq = idx & 3;
            float4 a = src[idx];
            __half2 h01 = __floats2half2_rn(a.x, a.y);
            __half2 h23 = __floats2half2_rn(a.z, a.w);
            uint2 u;
            u.x = *(uint32_t*)&h01;
            u.y = *(uint32_t*)&h23;
            *(uint2*)(smem + OFF_ASH + r * 48 + oq * 8) = u;
        }
    }

    // Prologue: chunks 0,1 -> stages 0,1
    #pragma unroll
    for (int p = 0; p < 2; p++) {
        const uint32_t stb = (uint32_t)p * STAGE_BYTES;
        #pragma unroll
        for (int i = 0; i < 8; i++) {
            cp16(sb + stb + cpdst + i * 2048,          xsrc + i * ROWSTEP + p * KT);
            cp16(sb + stb + TILE_B + cpdst + i * 2048, ysrc + i * ROWSTEP + p * KT);
        }
        CP_COMMIT();
    }

    float acc[4][8][4];
    #pragma unroll
    for (int mt = 0; mt < 4; mt++)
        #pragma unroll
        for (int nt = 0; nt < 8; nt++)
            #pragma unroll
            for (int q = 0; q < 4; q++) acc[mt][nt][q] = 0.0f;

    uint32_t af[2][4][4], bf[2][4][4];

    // Prologue tail: chunk 0 visible, load its ks0 fragments.
    CP_WAIT(1);
    __syncthreads();
    #pragma unroll
    for (int mt = 0; mt < 4; mt++)
        LDMX4(af[0][mt], sb + arowb + mt * 2048 + acolv[0]);
    #pragma unroll
    for (int nb = 0; nb < 4; nb++)
        LDMX4(bf[0][nb], sb + browb + nb * 2048 + bcolv[0]);

    #pragma unroll
    for (int c = 0; c < KCHUNKS; c++) {
        const uint32_t stb  = (uint32_t)(c % 3) * STAGE_BYTES;
        const uint32_t stb1 = (uint32_t)((c + 1) % 3) * STAGE_BYTES;

        // Prefetch chunk c+2 (stage (c+2)%3): safe — barrier in iter c-1's
        // ks=3 separated the previous readers of that stage.
        if (c + 2 < KCHUNKS) {
            const uint32_t nstb = (uint32_t)((c + 2) % 3) * STAGE_BYTES;
            const int kb = (c + 2) * KT;
            #pragma unroll
            for (int i = 0; i < 8; i++) {
                cp16(sb + nstb + cpdst + i * 2048,
                     xsrc + i * ROWSTEP + kb);
                cp16(sb + nstb + TILE_B + cpdst + i * 2048,
                     ysrc + i * ROWSTEP + kb);
            }
        }
        CP_COMMIT();         // empty group at tail keeps accounting uniform

        #pragma unroll
        for (int ks = 0; ks < 4; ks++) {
            const int cur = ks & 1;
            const int nxt = cur ^ 1;
            if (ks < 3) {
                #pragma unroll
                for (int mt = 0; mt < 4; mt++)
                    LDMX4(af[nxt][mt],
                          sb + stb + arowb + mt * 2048 + acolv[ks + 1]);
                #pragma unroll
                for (int nb = 0; nb < 4; nb++)
                    LDMX4(bf[nxt][nb],
                          sb + stb + browb + nb * 2048 + bcolv[ks + 1]);
            } else if (c + 1 < KCHUNKS) {
                // Cross-chunk prefetch: chunk c+1 group retired in every
                // thread (CP_WAIT), then barrier -> copies globally visible.
                // Barrier also licenses iter c+1's prefetch to overwrite
                // stage c%3 (all its reads were issued at ks=2).
                CP_WAIT(1);
                __syncthreads();
                #pragma unroll
                for (int mt = 0; mt < 4; mt++)
                    LDMX4(af[nxt][mt],
                          sb + stb1 + arowb + mt * 2048 + acolv[0]);
                #pragma unroll
                for (int nb = 0; nb < 4; nb++)
                    LDMX4(bf[nxt][nb],
                          sb + stb1 + browb + nb * 2048 + bcolv[0]);
            }
            #pragma unroll
            for (int mt = 0; mt < 4; mt++)
                #pragma unroll
                for (int nt = 0; nt < 8; nt++)
                    MMAF16(acc[mt][nt], af[cur][mt],
                           bf[cur][nt >> 1][(nt & 1) * 2],
                           bf[cur][nt >> 1][(nt & 1) * 2 + 1]);
        }
    }

    // ---------------- Epilogue (register-direct, no barriers) ---------------
    float oa[4][2][4];
    #pragma unroll
    for (int mt = 0; mt < 4; mt++)
        #pragma unroll
        for (int b = 0; b < 2; b++)
            #pragma unroll
            for (int q = 0; q < 4; q++) oa[mt][b][q] = 0.0f;

    #pragma unroll
    for (int kt = 0; kt < 4; kt++) {          // k-tile within warp's 64 cols
        const int ktg = warp_n * 4 + kt;
        uint32_t bfr[4];
        LDMX4T(bfr, sb + OFF_ASH + (uint32_t)(ktg * 16 + (lane & 15)) * 48
                    + (uint32_t)(lane >> 4) * 16);
        #pragma unroll
        for (int mt = 0; mt < 4; mt++) {
            const float* c0 = acc[mt][2 * kt];
            const float* c1 = acc[mt][2 * kt + 1];
            __half2 h0 = __floats2half2_rn(
                __expf(c0[0] * (2.0f * GAMMA)) - 1.0f,
                __expf(c0[1] * (2.0f * GAMMA)) - 1.0f);
            __half2 h1 = __floats2half2_rn(
                __expf(c0[2] * (2.0f * GAMMA)) - 1.0f,
                __expf(c0[3] * (2.0f * GAMMA)) - 1.0f);
            __half2 h2 = __floats2half2_rn(
                __expf(c1[0] * (2.0f * GAMMA)) - 1.0f,
                __expf(c1[1] * (2.0f * GAMMA)) - 1.0f);
            __half2 h3 = __floats2half2_rn(
                __expf(c1[2] * (2.0f * GAMMA)) - 1.0f,
                __expf(c1[3] * (2.0f * GAMMA)) - 1.0f);
            uint32_t afr[4];
            afr[0] = *(uint32_t*)&h0;
            afr[1] = *(uint32_t*)&h1;
            afr[2] = *(uint32_t*)&h2;
            afr[3] = *(uint32_t*)&h3;
            MMAF16(oa[mt][0], afr, bfr[0], bfr[1]);
            MMAF16(oa[mt][1], afr, bfr[2], bfr[3]);
        }
    }

    #pragma unroll
    for (int mt = 0; mt < 4; mt++) {
        const int r = row0 + warp_m * 64 + mt * 16 + (lane >> 2);
        const float xs0 = g_xs[r];
        const float xs1 = g_xs[r + 8];
        #pragma unroll
        for (int b = 0; b < 2; b++) {
            const int cc = b * 8 + 2 * (lane & 3);
            atomicAdd(&out[(size_t)r * NOUT + cc],           oa[mt][b][0] * xs0);
            atomicAdd(&out[(size_t)r * NOUT + cc + 1],       oa[mt][b][1] * xs0);
            atomicAdd(&out[(size_t)(r + 8) * NOUT + cc],     oa[mt][b][2] * xs1);
            atomicAdd(&out[(size_t)(r + 8) * NOUT + cc + 1], oa[mt][b][3] * xs1);
        }
    }
}

// ---------------------------------------------------------------------------
extern "C" void kernel_launch(void* const* d_in, const int* in_sizes, int n_in,
                              void* d_out, int out_size) {
    const float* X     = (const float*)d_in[0];
    const float* TX    = (const float*)d_in[1];
    const float* alpha = (const float*)d_in[2];
    float* out = (float*)d_out;

    cudaFuncSetAttribute(rbf_hmma_kernel,
                         cudaFuncAttributeMaxDynamicSharedMemorySize, SMEM_BYTES);

    zero_s_kernel<<<1, 32>>>();
    prep_kernel<<<NTEST + NTRAIN, 128>>>(X, TX, alpha);
    init_out_kernel<<<(NTEST * NOUT) / 256, 256>>>(out);
    rbf_hmma_kernel<<<dim3(NTEST / BM, NTRAIN / BN), 128, SMEM_BYTES>>>(out);
}